// round 14
// baseline (speedup 1.0000x reference)
#include <cuda_runtime.h>
#include <cuda_fp16.h>
#include <cstdint>

// ============================================================================
// out[n,c,hw] = sum_k g[(c-k)&255] * act[n,k,hw]   (circulant inverse GEMM)
// fp16 mma.sync m16n8k16 (fp32 accum), liveness-masked A-blocks.
// Two-phase staging: chunks 0-3 staged, LDGs for 4-7 issued (complete under
// phase-1 compute), tiles finishing in phase 1 stored early (writes overlap
// phase-2 compute). Exactly two __syncthreads in the whole main path.
// CTA: 256c x 64hw, 256 threads (8 warps = 4M x 2N), 2 CTAs/SM.
// ============================================================================

__device__ __align__(16) __half aext_g[256 * 32];
__device__ uint32_t g_mask;

// ---------------------------------------------------------------------------
// Prep: g = IDFT(1/DFT(delta - padded_rolled_ricker)); fp16 circulant table
// + per-block liveness mask. Fast: 27-tap forward, Hermitian IDFT, ballot mask.
// ---------------------------------------------------------------------------
__global__ void prep_kernel(const float* __restrict__ filt) {
    __shared__ float f_s[27];
    __shared__ float twc[256];
    __shared__ float tws[256];
    __shared__ float gre[256];
    __shared__ float gim[256];
    __shared__ float g_s[256];

    int t = threadIdx.x;
    if (t < 27) f_s[t] = filt[t];

    float s, c;
    sincospif(-(float)t / 128.0f, &s, &c);
    twc[t] = c;
    tws[t] = s;
    __syncthreads();

    // Mhat[t] = 1 - sum_i filt[i] * tw[(t*(243+i)) & 255]
    float re = 1.0f, im = 0.0f;
#pragma unroll
    for (int i = 0; i < 27; ++i) {
        int idx = (t * (243 + i)) & 255;
        re = fmaf(-f_s[i], twc[idx], re);
        im = fmaf(-f_s[i], tws[idx], im);
    }
    float inv = 1.0f / (re * re + im * im);
    gre[t] = re * inv;
    gim[t] = -im * inv;
    __syncthreads();

    // Hermitian IDFT
    {
        float a = gre[0] + gre[128] * twc[(t * 128) & 255];
        for (int q = 1; q < 128; ++q) {
            int idx = (t * q) & 255;
            a = fmaf(2.0f * gre[q], twc[idx], a);
            a = fmaf(2.0f * gim[q], tws[idx], a);
        }
        g_s[t] = a * (1.0f / 256.0f);
    }
    __syncthreads();

    for (int kk = 0; kk < 32; ++kk)
        aext_g[t * 32 + kk] = __float2half_rn(g_s[(t - kk) & 255]);

    // Block liveness via ballot: block b covers g indices [16b-31, 16b+15].
    if (t < 32) {
        float mx = 0.0f;
        if (t < 16) {
#pragma unroll 1
            for (int d = 0; d < 47; ++d)
                mx = fmaxf(mx, fabsf(g_s[(16 * t - 31 + d) & 255]));
        }
        uint32_t m = __ballot_sync(0xFFFFFFFFu, (t < 16) && (mx > 1e-5f)) & 0xFFFFu;
        if (t == 0) g_mask = m;
    }
}

// ---------------------------------------------------------------------------
// PTX helpers (base PTX: ldmatrix + mma.sync, sm_80 features)
// ---------------------------------------------------------------------------
__device__ __forceinline__ uint32_t smem_u32(const void* p) {
    uint32_t a;
    asm("{ .reg .u64 t; cvta.to.shared.u64 t, %1; cvt.u32.u64 %0, t; }"
        : "=r"(a) : "l"(p));
    return a;
}
__device__ __forceinline__ void ldsm_x4(uint32_t* r, uint32_t addr) {
    asm volatile("ldmatrix.sync.aligned.m8n8.x4.shared.b16 {%0,%1,%2,%3}, [%4];"
                 : "=r"(r[0]), "=r"(r[1]), "=r"(r[2]), "=r"(r[3]) : "r"(addr));
}
__device__ __forceinline__ void ldsm_x4_t(uint32_t* r, uint32_t addr) {
    asm volatile("ldmatrix.sync.aligned.m8n8.x4.trans.shared.b16 {%0,%1,%2,%3}, [%4];"
                 : "=r"(r[0]), "=r"(r[1]), "=r"(r[2]), "=r"(r[3]) : "r"(addr));
}
__device__ __forceinline__ void mma16816(float* d, const uint32_t* a,
                                         const uint32_t* b) {
    asm volatile(
        "mma.sync.aligned.m16n8k16.row.col.f32.f16.f16.f32 "
        "{%0,%1,%2,%3},{%4,%5,%6,%7},{%8,%9},{%0,%1,%2,%3};"
        : "+f"(d[0]), "+f"(d[1]), "+f"(d[2]), "+f"(d[3])
        : "r"(a[0]), "r"(a[1]), "r"(a[2]), "r"(a[3]), "r"(b[0]), "r"(b[1]));
}

// SMEM layout
static constexpr uint32_t A_PITCH = 80;    // 32 fp16 (64B) + 16B pad
static constexpr uint32_t B_PITCH = 144;   // 64 fp16 (128B) + 16B pad
static constexpr uint32_t OFF_A   = 0;                  // 256*80 = 20480
static constexpr uint32_t OFF_B   = 20480;              // 8 chunk buffers
static constexpr uint32_t B_BUF   = 32 * B_PITCH;       // 4608
static constexpr uint32_t SMEM_BYTES = 20480 + 8 * B_BUF;  // 57344

__global__ __launch_bounds__(256, 2)
void mma_toeplitz_kernel(const float* __restrict__ act, float* __restrict__ out) {
    extern __shared__ __align__(128) char smem[];
    const uint32_t sb = smem_u32(smem);
    const int tid = threadIdx.x;
    const int lid = tid & 31;
    const int wid = tid >> 5;
    const int warp_m = wid >> 1;   // 0..3 -> 64 c each
    const int warp_n = wid & 1;    // 0..1 -> 32 hw each
    const int hw0 = blockIdx.x * 64;
    const int n   = blockIdx.y;

    const float* actn = act + (size_t)n * (256 * 4096);
    float*       outn = out + (size_t)n * (256 * 4096);

    const uint32_t mask = g_mask;

    // Per-mt last alive chunk
    int last_j[4];
#pragma unroll
    for (int mt = 0; mt < 4; ++mt) {
        last_j[mt] = 0;
#pragma unroll
        for (int j = 0; j < 8; ++j)
            if ((mask >> ((warp_m * 4 + mt + 32 - 2 * j) & 15)) & 1) last_j[mt] = j;
    }

    // Copy circulant A table gmem -> smem (64B rows -> pitch 80)
    {
        const float4* src = (const float4*)aext_g;
#pragma unroll
        for (int l = 0; l < 4; ++l) {
            int i = tid + l * 256;
            uint32_t dst = (uint32_t)(i >> 2) * A_PITCH + (uint32_t)(i & 3) * 16;
            *(float4*)(smem + OFF_A + dst) = src[i];
        }
    }

    // Staging coordinates: thread owns k row cr, hw cols [cc*8, cc*8+8)
    const int cr = tid >> 3;          // 0..31
    const int cc = tid & 7;           // 0..7
    const float* gsrc = &actn[(size_t)cr * 4096 + hw0 + cc * 8];
    const uint32_t sts = sb + OFF_B + (uint32_t)cr * B_PITCH + (uint32_t)cc * 16;

#define STS_CHUNK(q, x0, x1)                                                 \
    do {                                                                     \
        __half2 h0 = __floats2half2_rn((x0).x, (x0).y);                      \
        __half2 h1 = __floats2half2_rn((x0).z, (x0).w);                      \
        __half2 h2 = __floats2half2_rn((x1).x, (x1).y);                      \
        __half2 h3 = __floats2half2_rn((x1).z, (x1).w);                      \
        asm volatile("st.shared.v4.b32 [%0], {%1,%2,%3,%4};"                 \
                     :: "r"(sts + (uint32_t)(q) * B_BUF),                    \
                        "r"(*(uint32_t*)&h0), "r"(*(uint32_t*)&h1),          \
                        "r"(*(uint32_t*)&h2), "r"(*(uint32_t*)&h3)           \
                     : "memory");                                            \
    } while (0)

    // ---- Phase A: stage chunks 0-3; issue LDGs for 4-7 --------------------
#pragma unroll
    for (int q = 0; q < 4; ++q) {
        float4 a0 = *(const float4*)(gsrc + (size_t)q * 32 * 4096);
        float4 a1 = *(const float4*)(gsrc + (size_t)q * 32 * 4096 + 4);
        STS_CHUNK(q, a0, a1);
    }
    float4 v0[4], v1[4];
#pragma unroll
    for (int q = 0; q < 4; ++q) {
        v0[q] = *(const float4*)(gsrc + (size_t)(q + 4) * 32 * 4096);
        v1[q] = *(const float4*)(gsrc + (size_t)(q + 4) * 32 * 4096 + 4);
    }
    __syncthreads();   // A table + chunks 0-3 visible; LDGs 4-7 in flight

    float acc[4][4][4] = {};

#define COMPUTE_CHUNK(j)                                                     \
    do {                                                                     \
        int al[4];                                                           \
        int any = 0;                                                         \
        _Pragma("unroll")                                                    \
        for (int mt = 0; mt < 4; ++mt) {                                     \
            al[mt] = (mask >> ((warp_m * 4 + mt + 32 - 2 * (j)) & 15)) & 1;  \
            any |= al[mt];                                                   \
        }                                                                    \
        if (any) {                                                           \
            const uint32_t bbase = sb + OFF_B + (uint32_t)(j) * B_BUF;       \
            _Pragma("unroll")                                                \
            for (int step = 0; step < 2; ++step) {                           \
                uint32_t brow = (uint32_t)(step * 16 + (lid & 15));          \
                uint32_t Bf[2][4];                                           \
                _Pragma("unroll")                                            \
                for (int bh = 0; bh < 2; ++bh) {                             \
                    uint32_t bcol =                                          \
                        (uint32_t)(warp_n * 32 + bh * 16 + ((lid >> 4) << 3));\
                    ldsm_x4_t(Bf[bh], bbase + brow * B_PITCH + bcol * 2);    \
                }                                                            \
                _Pragma("unroll")                                            \
                for (int mt = 0; mt < 4; ++mt) {                             \
                    if (!al[mt]) continue;                                   \
                    int sbase = ((warp_m * 64 + mt * 16) - (j) * 32) & 255;  \
                    uint32_t arow = (uint32_t)(sbase + (lid & 15));          \
                    uint32_t acol = (uint32_t)(step * 32 + ((lid >> 4) << 4));\
                    uint32_t Af[4];                                          \
                    ldsm_x4(Af, sb + OFF_A + arow * A_PITCH + acol);         \
                    mma16816(acc[mt][0], Af, Bf[0]);                         \
                    mma16816(acc[mt][1], Af, Bf[0] + 2);                     \
                    mma16816(acc[mt][2], Af, Bf[1]);                         \
                    mma16816(acc[mt][3], Af, Bf[1] + 2);                     \
                }                                                            \
            }                                                                \
        }                                                                    \
    } while (0)

#define STORE_MT(mt)                                                         \
    do {                                                                     \
        int c = warp_m * 64 + (mt) * 16 + (lid >> 2);                        \
        _Pragma("unroll")                                                    \
        for (int nq = 0; nq < 4; ++nq) {                                     \
            int col = hw0 + warp_n * 32 + nq * 8 + (lid & 3) * 2;            \
            *(float2*)&outn[(size_t)c * 4096 + col] =                        \
                make_float2(acc[mt][nq][0], acc[mt][nq][1]);                 \
            *(float2*)&outn[(size_t)(c + 8) * 4096 + col] =                  \
                make_float2(acc[mt][nq][2], acc[mt][nq][3]);                 \
        }                                                                    \
    } while (0)

    // ---- Phase 1 compute: j = 0..3 (reads for 4-7 landing meanwhile) ------
#pragma unroll
    for (int j = 0; j < 4; ++j) COMPUTE_CHUNK(j);

    // Stage chunks 4-7 (buffers 4-7 unread -> no hazard before sync)
#pragma unroll
    for (int q = 0; q < 4; ++q) STS_CHUNK(q + 4, v0[q], v1[q]);

    // Early stores: tiles complete after phase 1 (overlap phase-2 compute)
#pragma unroll
    for (int mt = 0; mt < 4; ++mt)
        if (last_j[mt] < 4) STORE_MT(mt);

    __syncthreads();   // chunks 4-7 visible

    // ---- Phase 2 compute: j = 4..7 ----------------------------------------
#pragma unroll
    for (int j = 4; j < 8; ++j) COMPUTE_CHUNK(j);

#pragma unroll
    for (int mt = 0; mt < 4; ++mt)
        if (last_j[mt] >= 4) STORE_MT(mt);

#undef STS_CHUNK
#undef COMPUTE_CHUNK
#undef STORE_MT
}

// ---------------------------------------------------------------------------
extern "C" void kernel_launch(void* const* d_in, const int* in_sizes, int n_in,
                              void* d_out, int out_size) {
    const float* act;
    const float* filt;
    if (n_in >= 2 && in_sizes[0] == 27) {
        filt = (const float*)d_in[0];
        act  = (const float*)d_in[1];
    } else {
        act  = (const float*)d_in[0];
        filt = (const float*)d_in[1];
    }

    cudaFuncSetAttribute(mma_toeplitz_kernel,
                         cudaFuncAttributeMaxDynamicSharedMemorySize, SMEM_BYTES);

    prep_kernel<<<1, 256>>>(filt);

    dim3 grid(4096 / 64, 32);   // (64, 32) = 2048 CTAs
    mma_toeplitz_kernel<<<grid, 256, SMEM_BYTES>>>(act, (float*)d_out);
}